// round 16
// baseline (speedup 1.0000x reference)
#include <cuda_runtime.h>
#include <cuda_fp16.h>

// Problem constants (fixed shapes per reference)
#define NSUM 6400
#define NMAX 64
#define MDIM 16
#define HDIM 32
#define ODIM 32
#define EDGES 51200

// Scratch: fp16 node-feature buffers + CSR structures.
// g_hw : converted input W, 64 rows x 16 halves = 128 uint4/node (13.1 MB)
// g_hh : ping/pong hidden h, 64 rows x 32 halves = 256 uint4/node (2 x 26.2 MB)
__device__ uint4 g_hw[NSUM * 128];
__device__ uint4 g_hh[2][NSUM * 256];
__device__ int g_cnt[NSUM];                    // zero-init at load; k_scan re-zeroes
__device__ int g_off[NSUM + 1];
__device__ int g_cur[NSUM];
__device__ int g_esrc[EDGES];

// ---- packed fp32x2 helpers (Blackwell dual-FMA; full fp32 precision) ----
__device__ __forceinline__ unsigned long long pack2(float lo, float hi) {
    unsigned long long r;
    asm("mov.b64 %0, {%1, %2};" : "=l"(r) : "f"(lo), "f"(hi));
    return r;
}
__device__ __forceinline__ unsigned long long pack2dup(float v) {
    unsigned long long r;
    asm("mov.b64 %0, {%1, %1};" : "=l"(r) : "f"(v));
    return r;
}
__device__ __forceinline__ void fma2(unsigned long long& d,
                                     unsigned long long a, unsigned long long b) {
    asm("fma.rn.f32x2 %0, %1, %2, %0;" : "+l"(d) : "l"(a), "l"(b));
}
__device__ __forceinline__ float2 unpack2(unsigned long long v) {
    float lo, hi;
    asm("mov.b64 {%0, %1}, %2;" : "=f"(lo), "=f"(hi) : "l"(v));
    return make_float2(lo, hi);
}

// ---- fp16 pack/unpack (storage only; all math stays fp32) ----
__device__ __forceinline__ float2 h2f(unsigned int w) {
    __half2 h = *reinterpret_cast<__half2*>(&w);
    return __half22float2(h);
}
__device__ __forceinline__ unsigned int f2h(float a, float b) {
    __half2 h = __floats2half2_rn(a, b);
    return *reinterpret_cast<unsigned int*>(&h);
}

// ---------------------------------------------------------------------------
// Input conversion: W fp32 -> g_hw fp16 (one-shot streaming kernel)
// ---------------------------------------------------------------------------
__global__ void k_cvt(const float* __restrict__ W) {
    int i = blockIdx.x * blockDim.x + threadIdx.x;   // over float4s
    if (i < NSUM * NMAX * MDIM / 4) {
        float4 t = ((const float4*)W)[i];
        ((uint2*)g_hw)[i] = make_uint2(f2h(t.x, t.y), f2h(t.z, t.w));
    }
}

// ---------------------------------------------------------------------------
// CSR build: count -> scan (self-cleaning) -> scatter
// ---------------------------------------------------------------------------
__global__ void k_count(const int* __restrict__ dst) {
    int e = blockIdx.x * blockDim.x + threadIdx.x;
    if (e < EDGES) atomicAdd(&g_cnt[dst[e]], 1);
}

__global__ void k_scan() {
    __shared__ int part[1024];
    int tid = threadIdx.x;
    const int CH = (NSUM + 1023) / 1024;  // 7
    int base = tid * CH;
    int s = 0;
    #pragma unroll
    for (int i = 0; i < CH; i++) {
        int idx = base + i;
        if (idx < NSUM) s += g_cnt[idx];
    }
    part[tid] = s;
    __syncthreads();
    int own = s;
    for (int d = 1; d < 1024; d <<= 1) {
        int v = (tid >= d) ? part[tid - d] : 0;
        __syncthreads();
        part[tid] += v;
        __syncthreads();
    }
    int run = part[tid] - own;
    #pragma unroll
    for (int i = 0; i < CH; i++) {
        int idx = base + i;
        if (idx < NSUM) {
            g_off[idx] = run;
            g_cur[idx] = run;
            run += g_cnt[idx];
            g_cnt[idx] = 0;          // self-clean for the next replay
        }
    }
    if (tid == 1023) g_off[NSUM] = EDGES;
}

__global__ void k_scatter(const int* __restrict__ src, const int* __restrict__ dst) {
    int e = blockIdx.x * blockDim.x + threadIdx.x;
    if (e < EDGES) {
        int p = atomicAdd(&g_cur[dst[e]], 1);
        g_esrc[p] = src[e];
    }
}

// ---------------------------------------------------------------------------
// Warp-per-NODE fused GIN layer, fp16 storage everywhere (validated R15
// pattern, now generalized to D=16 as well).
// Node block = 64 rows x DIN halves = NMAX*DIN/8 uint4. Lane owns NSLOT
// contiguous uint4 slots {m*32 + lane}: every warp-LDG is a contiguous 512B
// block (4 L1tex wavefronts). slot -> row = slot/U4R, halfcol = (slot%U4R)*8.
// All accumulation fp32 (convert on load). MLP: f32x2 dual-FMA in fp32 smem.
// Non-POOL output stored fp16; POOL reduces in-warp -> fp32 dout.
// Dynamic smem: 8 warps x 64 x 36 floats (x/hid union).
// ---------------------------------------------------------------------------
template <int DIN, bool RELU_OUT, bool POOL>
__global__ __launch_bounds__(256, 2) void k_layer(
    const uint4* __restrict__ hb, uint4* __restrict__ hob,
    const float* __restrict__ epsv, int layer,
    const float* __restrict__ W1, const float* __restrict__ b1,
    const float* __restrict__ W2, const float* __restrict__ b2,
    float* __restrict__ dout)
{
    constexpr int PAD   = 36;              // smem row stride (floats)
    constexpr int U4R   = DIN / 8;         // uint4 per row (2 or 4)
    constexpr int NB    = NMAX * U4R;      // uint4 per node block (128/256)
    constexpr int NSLOT = NB / 32;         // slots per lane (4 or 8)
    constexpr int RINC  = 32 / U4R;        // row increment per m (16 or 8)

    __shared__ float sW1[DIN * 32];
    __shared__ float sW2[32 * 32];
    __shared__ float sb1[32], sb2[32];
    extern __shared__ float sxh_dyn[];     // 8 x 64 x PAD floats

    int tid = threadIdx.x;
    int wid = tid >> 5, lane = tid & 31;
    int lr = lane >> 2, q = lane & 3;

    for (int i = tid; i < DIN * 32; i += 256) sW1[i] = W1[i];
    for (int i = tid; i < 32 * 32;  i += 256) sW2[i] = W2[i];
    if (tid < 32) { sb1[tid] = b1[tid]; sb2[tid] = b2[tid]; }
    float ep1 = 1.0f + epsv[layer];
    __syncthreads();

    float* sxw = sxh_dyn + wid * (64 * PAD);

    // staging coordinates for lane's slot set (slot = m*32 + lane)
    const int stg_row0 = lane / U4R;
    const int stg_colf = (lane % U4R) * 8;

    for (int n = blockIdx.x * 8 + wid; n < NSUM; n += gridDim.x * 8) {
        int e0 = g_off[n], e1 = g_off[n + 1];

        // ---- fp16 gather: acc = (1+eps)*h[n] + sum_neighbors h[src] ----
        float accf[NSLOT * 8];
        {
            const uint4* hn = hb + (size_t)n * NB + lane;
            #pragma unroll
            for (int m = 0; m < NSLOT; m++) {
                uint4 t = hn[m * 32];
                float2 f0 = h2f(t.x), f1 = h2f(t.y), f2 = h2f(t.z), f3 = h2f(t.w);
                accf[m*8+0] = ep1 * f0.x; accf[m*8+1] = ep1 * f0.y;
                accf[m*8+2] = ep1 * f1.x; accf[m*8+3] = ep1 * f1.y;
                accf[m*8+4] = ep1 * f2.x; accf[m*8+5] = ep1 * f2.y;
                accf[m*8+6] = ep1 * f3.x; accf[m*8+7] = ep1 * f3.y;
            }
        }
        for (int base = e0; base < e1; base += 32) {
            int cnt = min(32, e1 - base);
            int id = (lane < cnt) ? g_esrc[base + lane] : 0;
            int e = 0;
            if (DIN == 16) {
                // 2-edge-wide register-buffered gather
                for (; e + 2 <= cnt; e += 2) {
                    int sa = __shfl_sync(0xffffffffu, id, e);
                    int sb = __shfl_sync(0xffffffffu, id, e + 1);
                    const uint4* pa = hb + (size_t)sa * NB + lane;
                    const uint4* pb = hb + (size_t)sb * NB + lane;
                    uint4 ta[NSLOT], tb[NSLOT];
                    #pragma unroll
                    for (int m = 0; m < NSLOT; m++) ta[m] = pa[m * 32];
                    #pragma unroll
                    for (int m = 0; m < NSLOT; m++) tb[m] = pb[m * 32];
                    #pragma unroll
                    for (int m = 0; m < NSLOT; m++) {
                        float2 f0 = h2f(ta[m].x), f1 = h2f(ta[m].y);
                        float2 f2 = h2f(ta[m].z), f3 = h2f(ta[m].w);
                        accf[m*8+0] += f0.x; accf[m*8+1] += f0.y;
                        accf[m*8+2] += f1.x; accf[m*8+3] += f1.y;
                        accf[m*8+4] += f2.x; accf[m*8+5] += f2.y;
                        accf[m*8+6] += f3.x; accf[m*8+7] += f3.y;
                    }
                    #pragma unroll
                    for (int m = 0; m < NSLOT; m++) {
                        float2 f0 = h2f(tb[m].x), f1 = h2f(tb[m].y);
                        float2 f2 = h2f(tb[m].z), f3 = h2f(tb[m].w);
                        accf[m*8+0] += f0.x; accf[m*8+1] += f0.y;
                        accf[m*8+2] += f1.x; accf[m*8+3] += f1.y;
                        accf[m*8+4] += f2.x; accf[m*8+5] += f2.y;
                        accf[m*8+6] += f3.x; accf[m*8+7] += f3.y;
                    }
                }
                if (e < cnt) {
                    int sa = __shfl_sync(0xffffffffu, id, e);
                    const uint4* pa = hb + (size_t)sa * NB + lane;
                    #pragma unroll
                    for (int m = 0; m < NSLOT; m++) {
                        uint4 t = pa[m * 32];
                        float2 f0 = h2f(t.x), f1 = h2f(t.y);
                        float2 f2 = h2f(t.z), f3 = h2f(t.w);
                        accf[m*8+0] += f0.x; accf[m*8+1] += f0.y;
                        accf[m*8+2] += f1.x; accf[m*8+3] += f1.y;
                        accf[m*8+4] += f2.x; accf[m*8+5] += f2.y;
                        accf[m*8+6] += f3.x; accf[m*8+7] += f3.y;
                    }
                }
            } else {
                // pointer-pipelined gather (next address precomputed)
                int sa0 = __shfl_sync(0xffffffffu, id, 0);
                const uint4* pa = hb + (size_t)sa0 * NB + lane;
                for (; e < cnt; e++) {
                    int en = (e + 1 < cnt) ? e + 1 : e;
                    int sn = __shfl_sync(0xffffffffu, id, en);
                    const uint4* pn = hb + (size_t)sn * NB + lane;
                    #pragma unroll
                    for (int m = 0; m < NSLOT; m++) {
                        uint4 t = pa[m * 32];
                        float2 f0 = h2f(t.x), f1 = h2f(t.y);
                        float2 f2 = h2f(t.z), f3 = h2f(t.w);
                        accf[m*8+0] += f0.x; accf[m*8+1] += f0.y;
                        accf[m*8+2] += f1.x; accf[m*8+3] += f1.y;
                        accf[m*8+4] += f2.x; accf[m*8+5] += f2.y;
                        accf[m*8+6] += f3.x; accf[m*8+7] += f3.y;
                    }
                    pa = pn;
                }
            }
        }
        // stage x into this warp's smem slice at (row, col) of each slot
        #pragma unroll
        for (int m = 0; m < NSLOT; m++) {
            float* p = &sxw[(stg_row0 + m * RINC) * PAD + stg_colf];
            ((float4*)p)[0] = make_float4(accf[m*8+0], accf[m*8+1],
                                          accf[m*8+2], accf[m*8+3]);
            ((float4*)p)[1] = make_float4(accf[m*8+4], accf[m*8+5],
                                          accf[m*8+6], accf[m*8+7]);
        }
        __syncwarp();

        // ---- hidden: hid = relu(x @ W1 + b1); lane: 8 rows x 4 col-pairs ----
        unsigned long long h2v[32];
        {
            float4 bb0 = *(const float4*)&sb1[q * 8];
            float4 bb1 = *(const float4*)&sb1[q * 8 + 4];
            unsigned long long bp[4] = {pack2(bb0.x, bb0.y), pack2(bb0.z, bb0.w),
                                        pack2(bb1.x, bb1.y), pack2(bb1.z, bb1.w)};
            #pragma unroll
            for (int m = 0; m < 8; m++)
                #pragma unroll
                for (int p = 0; p < 4; p++) h2v[m * 4 + p] = bp[p];
        }
        #pragma unroll
        for (int kb = 0; kb < DIN / 4; kb++) {
            float4 xq[8];
            #pragma unroll
            for (int m = 0; m < 8; m++)
                xq[m] = *(const float4*)&sxw[(lr + 8 * m) * PAD + kb * 4];
            #pragma unroll
            for (int kk = 0; kk < 4; kk++) {
                int k = kb * 4 + kk;
                float4 w0 = *(const float4*)&sW1[k * 32 + q * 8];
                float4 w1 = *(const float4*)&sW1[k * 32 + q * 8 + 4];
                unsigned long long wp[4] = {pack2(w0.x, w0.y), pack2(w0.z, w0.w),
                                            pack2(w1.x, w1.y), pack2(w1.z, w1.w)};
                #pragma unroll
                for (int m = 0; m < 8; m++) {
                    float xv = (kk == 0) ? xq[m].x : (kk == 1) ? xq[m].y
                             : (kk == 2) ? xq[m].z : xq[m].w;
                    unsigned long long xa = pack2dup(xv);
                    #pragma unroll
                    for (int p = 0; p < 4; p++)
                        fma2(h2v[m * 4 + p], xa, wp[p]);
                }
            }
        }
        __syncwarp();   // all x reads done before hid overwrites the buffer
        #pragma unroll
        for (int m = 0; m < 8; m++) {
            float2 p0 = unpack2(h2v[m * 4 + 0]);
            float2 p1 = unpack2(h2v[m * 4 + 1]);
            float2 p2 = unpack2(h2v[m * 4 + 2]);
            float2 p3 = unpack2(h2v[m * 4 + 3]);
            float* p = &sxw[(lr + 8 * m) * PAD + q * 8];
            ((float4*)p)[0] = make_float4(fmaxf(p0.x, 0.f), fmaxf(p0.y, 0.f),
                                          fmaxf(p1.x, 0.f), fmaxf(p1.y, 0.f));
            ((float4*)p)[1] = make_float4(fmaxf(p2.x, 0.f), fmaxf(p2.y, 0.f),
                                          fmaxf(p3.x, 0.f), fmaxf(p3.y, 0.f));
        }
        __syncwarp();

        // ---- output: out = hid @ W2 + b2 ----
        unsigned long long o2[32];
        {
            float4 bb0 = *(const float4*)&sb2[q * 8];
            float4 bb1 = *(const float4*)&sb2[q * 8 + 4];
            unsigned long long bp[4] = {pack2(bb0.x, bb0.y), pack2(bb0.z, bb0.w),
                                        pack2(bb1.x, bb1.y), pack2(bb1.z, bb1.w)};
            #pragma unroll
            for (int m = 0; m < 8; m++)
                #pragma unroll
                for (int p = 0; p < 4; p++) o2[m * 4 + p] = bp[p];
        }
        #pragma unroll
        for (int jb = 0; jb < 8; jb++) {
            float4 hq[8];
            #pragma unroll
            for (int m = 0; m < 8; m++)
                hq[m] = *(const float4*)&sxw[(lr + 8 * m) * PAD + jb * 4];
            #pragma unroll
            for (int jj = 0; jj < 4; jj++) {
                int j = jb * 4 + jj;
                float4 w0 = *(const float4*)&sW2[j * 32 + q * 8];
                float4 w1 = *(const float4*)&sW2[j * 32 + q * 8 + 4];
                unsigned long long wp[4] = {pack2(w0.x, w0.y), pack2(w0.z, w0.w),
                                            pack2(w1.x, w1.y), pack2(w1.z, w1.w)};
                #pragma unroll
                for (int m = 0; m < 8; m++) {
                    float hv = (jj == 0) ? hq[m].x : (jj == 1) ? hq[m].y
                             : (jj == 2) ? hq[m].z : hq[m].w;
                    unsigned long long ha = pack2dup(hv);
                    #pragma unroll
                    for (int p = 0; p < 4; p++)
                        fma2(o2[m * 4 + p], ha, wp[p]);
                }
            }
        }
        __syncwarp();   // hid reads done before next iteration stages x

        if (!POOL) {
            // store fp16: row = lr+8m, 8 half cols at q*8 -> one uint4
            uint4* ob = hob + (size_t)n * 256;
            #pragma unroll
            for (int m = 0; m < 8; m++) {
                float2 p0 = unpack2(o2[m * 4 + 0]);
                float2 p1 = unpack2(o2[m * 4 + 1]);
                float2 p2 = unpack2(o2[m * 4 + 2]);
                float2 p3 = unpack2(o2[m * 4 + 3]);
                float v[8] = {p0.x, p0.y, p1.x, p1.y, p2.x, p2.y, p3.x, p3.y};
                if (RELU_OUT) {
                    #pragma unroll
                    for (int i = 0; i < 8; i++) v[i] = fmaxf(v[i], 0.0f);
                }
                uint4 o;
                o.x = f2h(v[0], v[1]); o.y = f2h(v[2], v[3]);
                o.z = f2h(v[4], v[5]); o.w = f2h(v[6], v[7]);
                int grow = lr + 8 * m;
                ob[grow * 4 + q] = o;
            }
        } else {
            // sum over lane's 8 rows, then over lr (lane bits 2..4) -> all 64
            float o[8];
            #pragma unroll
            for (int i = 0; i < 8; i++) o[i] = 0.0f;
            #pragma unroll
            for (int m = 0; m < 8; m++) {
                float2 p0 = unpack2(o2[m * 4 + 0]);
                float2 p1 = unpack2(o2[m * 4 + 1]);
                float2 p2 = unpack2(o2[m * 4 + 2]);
                float2 p3 = unpack2(o2[m * 4 + 3]);
                o[0] += p0.x; o[1] += p0.y; o[2] += p1.x; o[3] += p1.y;
                o[4] += p2.x; o[5] += p2.y; o[6] += p3.x; o[7] += p3.y;
            }
            #pragma unroll
            for (int s = 4; s <= 16; s <<= 1) {
                #pragma unroll
                for (int i = 0; i < 8; i++)
                    o[i] += __shfl_xor_sync(0xffffffffu, o[i], s);
            }
            if (lane < 4) {
                float* p = &dout[n * 32 + q * 8];
                ((float4*)p)[0] = make_float4(o[0], o[1], o[2], o[3]);
                ((float4*)p)[1] = make_float4(o[4], o[5], o[6], o[7]);
            }
        }
    }
}

// ---------------------------------------------------------------------------
extern "C" void kernel_launch(void* const* d_in, const int* in_sizes, int n_in,
                              void* d_out, int out_size)
{
    const float* W    = (const float*)d_in[0];   // [6400, 64, 16]
    const int*   ei   = (const int*)d_in[1];     // [2, E] row-major
    const float* eps  = (const float*)d_in[2];   // [3]
    const float* W1_0 = (const float*)d_in[3];
    const float* b1_0 = (const float*)d_in[4];
    const float* W2_0 = (const float*)d_in[5];
    const float* b2_0 = (const float*)d_in[6];
    const float* W1_1 = (const float*)d_in[7];
    const float* b1_1 = (const float*)d_in[8];
    const float* W2_1 = (const float*)d_in[9];
    const float* b2_1 = (const float*)d_in[10];
    const float* W1_2 = (const float*)d_in[11];
    const float* b1_2 = (const float*)d_in[12];
    const float* W2_2 = (const float*)d_in[13];
    const float* b2_2 = (const float*)d_in[14];
    float* out = (float*)d_out;

    const int* src = ei;
    const int* dst = ei + EDGES;

    const int DYN = 8 * 64 * 36 * (int)sizeof(float);   // 73728 B
    cudaFuncSetAttribute(k_layer<16, true, false>,
                         cudaFuncAttributeMaxDynamicSharedMemorySize, DYN);
    cudaFuncSetAttribute(k_layer<32, true, false>,
                         cudaFuncAttributeMaxDynamicSharedMemorySize, DYN);
    cudaFuncSetAttribute(k_layer<32, false, true>,
                         cudaFuncAttributeMaxDynamicSharedMemorySize, DYN);

    // device pointers to the fp16 scratch buffers
    uint4 *hw_p, *hh0_p, *hh1_p;
    cudaGetSymbolAddress((void**)&hw_p,  g_hw);
    cudaGetSymbolAddress((void**)&hh0_p, g_hh);
    hh1_p = hh0_p + NSUM * 256;

    // Input conversion + CSR build (independent; cvt overlaps CSR work)
    k_cvt<<<(NSUM * NMAX * MDIM / 4 + 255) / 256, 256>>>(W);   // launch 0
    k_count<<<(EDGES + 255) / 256, 256>>>(dst);                 // launch 1
    k_scan<<<1, 1024>>>();                                       // launch 2
    k_scatter<<<(EDGES + 255) / 256, 256>>>(src, dst);          // launch 3

    const int GRID = 296;   // one persistent wave: 2 blocks x 148 SMs

    // Layer 0: g_hw fp16 (D=16) -> g_hh[0] fp16 (relu)         -- launch 4
    k_layer<16, true, false><<<GRID, 256, DYN>>>(hw_p, hh0_p, eps, 0,
                                                 W1_0, b1_0, W2_0, b2_0, nullptr);
    // Layer 1: g_hh[0] -> g_hh[1] fp16 (relu)                  -- launch 5
    k_layer<32, true, false><<<GRID, 256, DYN>>>(hh0_p, hh1_p, eps, 1,
                                                 W1_1, b1_1, W2_1, b2_1, nullptr);
    // Layer 2: g_hh[1] -> pooled fp32 d_out (no relu)          -- launch 6
    k_layer<32, false, true><<<GRID, 256, DYN>>>(hh1_p, nullptr, eps, 2,
                                                 W1_2, b1_2, W2_2, b2_2, out);
}

// round 17
// speedup vs baseline: 1.0474x; 1.0474x over previous
#include <cuda_runtime.h>
#include <cuda_fp16.h>

// Problem constants (fixed shapes per reference)
#define NSUM 6400
#define NMAX 64
#define MDIM 16
#define HDIM 32
#define ODIM 32
#define EDGES 51200

// Scratch: ping/pong fp16 h buffers + CSR structures + work queues.
__device__ uint4 g_hh[2][NSUM * 256];          // 2 x 26.2 MB
__device__ int g_cnt[NSUM];                    // zero-init; k_scan re-zeroes
__device__ int g_off[NSUM + 1];
__device__ int g_cur[NSUM];
__device__ int g_esrc[EDGES];
__device__ int g_work[4];                      // per-layer ticket counters

// ---- packed fp32x2 helpers (Blackwell dual-FMA; full fp32 precision) ----
__device__ __forceinline__ unsigned long long pack2(float lo, float hi) {
    unsigned long long r;
    asm("mov.b64 %0, {%1, %2};" : "=l"(r) : "f"(lo), "f"(hi));
    return r;
}
__device__ __forceinline__ unsigned long long pack2dup(float v) {
    unsigned long long r;
    asm("mov.b64 %0, {%1, %1};" : "=l"(r) : "f"(v));
    return r;
}
__device__ __forceinline__ void fma2(unsigned long long& d,
                                     unsigned long long a, unsigned long long b) {
    asm("fma.rn.f32x2 %0, %1, %2, %0;" : "+l"(d) : "l"(a), "l"(b));
}
__device__ __forceinline__ float2 unpack2(unsigned long long v) {
    float lo, hi;
    asm("mov.b64 {%0, %1}, %2;" : "=f"(lo), "=f"(hi) : "l"(v));
    return make_float2(lo, hi);
}

// ---- fp16 pack/unpack (storage only; all math stays fp32) ----
__device__ __forceinline__ float2 h2f(unsigned int w) {
    __half2 h = *reinterpret_cast<__half2*>(&w);
    return __half22float2(h);
}
__device__ __forceinline__ unsigned int f2h(float a, float b) {
    __half2 h = __floats2half2_rn(a, b);
    return *reinterpret_cast<unsigned int*>(&h);
}

// ---------------------------------------------------------------------------
// CSR build: count -> scan (self-cleaning; also resets work queues) -> scatter
// ---------------------------------------------------------------------------
__global__ void k_count(const int* __restrict__ dst) {
    int e = blockIdx.x * blockDim.x + threadIdx.x;
    if (e < EDGES) atomicAdd(&g_cnt[dst[e]], 1);
}

__global__ void k_scan() {
    __shared__ int part[1024];
    int tid = threadIdx.x;
    const int CH = (NSUM + 1023) / 1024;  // 7
    int base = tid * CH;
    int s = 0;
    #pragma unroll
    for (int i = 0; i < CH; i++) {
        int idx = base + i;
        if (idx < NSUM) s += g_cnt[idx];
    }
    part[tid] = s;
    __syncthreads();
    int own = s;
    for (int d = 1; d < 1024; d <<= 1) {
        int v = (tid >= d) ? part[tid - d] : 0;
        __syncthreads();
        part[tid] += v;
        __syncthreads();
    }
    int run = part[tid] - own;
    #pragma unroll
    for (int i = 0; i < CH; i++) {
        int idx = base + i;
        if (idx < NSUM) {
            g_off[idx] = run;
            g_cur[idx] = run;
            run += g_cnt[idx];
            g_cnt[idx] = 0;          // self-clean for the next replay
        }
    }
    if (tid == 1023) {
        g_off[NSUM] = EDGES;
        g_work[0] = 0; g_work[1] = 0; g_work[2] = 0; g_work[3] = 0;
    }
}

__global__ void k_scatter(const int* __restrict__ src, const int* __restrict__ dst) {
    int e = blockIdx.x * blockDim.x + threadIdx.x;
    if (e < EDGES) {
        int p = atomicAdd(&g_cur[dst[e]], 1);
        g_esrc[p] = src[e];
    }
}

// ---------------------------------------------------------------------------
// Warp-per-NODE fused GIN layer with DYNAMIC work-stealing node assignment.
// IN_HALF=false (layer 0): fp32 external input, D=16, linear float4 gather.
// IN_HALF=true  (layers 1/2): fp16 h buffer, D=32, contiguous uint4 gather.
// All accumulation fp32. MLP: f32x2 dual-FMA in fp32 smem (R15-validated).
// Non-POOL output stored fp16; POOL reduces in-warp -> fp32 dout.
// Node claims via atomicAdd ticket (lane 0, shfl-broadcast): smooths the
// degree-variance + persistent-wave tail at ~2.7 nodes/warp granularity.
// Dynamic smem: 8 warps x 64 x 36 floats (x/hid union).
// ---------------------------------------------------------------------------
template <int DIN, bool IN_HALF, bool RELU_OUT, bool POOL>
__global__ __launch_bounds__(256, 2) void k_layer(
    const float* __restrict__ ext_in, int in_buf, int out_buf,
    const float* __restrict__ epsv, int layer,
    const float* __restrict__ W1, const float* __restrict__ b1,
    const float* __restrict__ W2, const float* __restrict__ b2,
    float* __restrict__ dout)
{
    constexpr int PAD  = 36;               // smem row stride (floats)

    __shared__ float sW1[DIN * 32];
    __shared__ float sW2[32 * 32];
    __shared__ float sb1[32], sb2[32];
    extern __shared__ float sxh_dyn[];     // 8 x 64 x PAD floats

    int tid = threadIdx.x;
    int wid = tid >> 5, lane = tid & 31;
    int lr = lane >> 2, q = lane & 3;

    for (int i = tid; i < DIN * 32; i += 256) sW1[i] = W1[i];
    for (int i = tid; i < 32 * 32;  i += 256) sW2[i] = W2[i];
    if (tid < 32) { sb1[tid] = b1[tid]; sb2[tid] = b2[tid]; }
    float ep1 = 1.0f + epsv[layer];
    __syncthreads();

    float* sxw = sxh_dyn + wid * (64 * PAD);

    for (;;) {
        int n = 0;
        if (lane == 0) n = atomicAdd(&g_work[layer], 1);
        n = __shfl_sync(0xffffffffu, n, 0);
        if (n >= NSUM) break;

        int e0 = g_off[n], e1 = g_off[n + 1];

        if constexpr (!IN_HALF) {
            // ---- fp32 gather, D=16 (layer 0) — validated R14/R15 path ----
            constexpr int R4 = DIN / 4;        // 4
            constexpr int V4 = NMAX * R4;      // 256
            constexpr int MV = V4 / 32;        // 8
            const float4* h4 = (const float4*)ext_in;

            float4 acc[MV];
            {
                const float4* hn = h4 + (size_t)n * V4 + lane;
                #pragma unroll
                for (int m = 0; m < MV; m++) {
                    float4 t = hn[m * 32];
                    acc[m] = make_float4(ep1 * t.x, ep1 * t.y, ep1 * t.z, ep1 * t.w);
                }
            }
            for (int base = e0; base < e1; base += 32) {
                int cnt = min(32, e1 - base);
                int id = (lane < cnt) ? g_esrc[base + lane] : 0;
                int e = 0;
                for (; e + 2 <= cnt; e += 2) {
                    int sa = __shfl_sync(0xffffffffu, id, e);
                    int sb = __shfl_sync(0xffffffffu, id, e + 1);
                    const float4* pa = h4 + (size_t)sa * V4 + lane;
                    const float4* pb = h4 + (size_t)sb * V4 + lane;
                    float4 ta[MV], tb[MV];
                    #pragma unroll
                    for (int m = 0; m < MV; m++) ta[m] = pa[m * 32];
                    #pragma unroll
                    for (int m = 0; m < MV; m++) tb[m] = pb[m * 32];
                    #pragma unroll
                    for (int m = 0; m < MV; m++) {
                        acc[m].x += ta[m].x; acc[m].y += ta[m].y;
                        acc[m].z += ta[m].z; acc[m].w += ta[m].w;
                    }
                    #pragma unroll
                    for (int m = 0; m < MV; m++) {
                        acc[m].x += tb[m].x; acc[m].y += tb[m].y;
                        acc[m].z += tb[m].z; acc[m].w += tb[m].w;
                    }
                }
                if (e < cnt) {
                    int sa = __shfl_sync(0xffffffffu, id, e);
                    const float4* pa = h4 + (size_t)sa * V4 + lane;
                    #pragma unroll
                    for (int m = 0; m < MV; m++) {
                        float4 t = pa[m * 32];
                        acc[m].x += t.x; acc[m].y += t.y;
                        acc[m].z += t.z; acc[m].w += t.w;
                    }
                }
            }
            // stage: slot = m*32+lane; row = slot>>2, colf = (slot&3)*4; RINC=8
            #pragma unroll
            for (int m = 0; m < MV; m++) {
                int row = (lane >> 2) + m * 8;
                float* p = &sxw[row * PAD + (lane & 3) * 4];
                *(float4*)p = acc[m];
            }
        } else {
            // ---- fp16 gather, D=32 (layers 1/2) ----
            const uint4* hb = g_hh[in_buf];
            float accf[64];
            {
                const uint4* hn = hb + (size_t)n * 256 + lane;
                #pragma unroll
                for (int m = 0; m < 8; m++) {
                    uint4 t = hn[m * 32];
                    float2 f0 = h2f(t.x), f1 = h2f(t.y), f2 = h2f(t.z), f3 = h2f(t.w);
                    accf[m*8+0] = ep1 * f0.x; accf[m*8+1] = ep1 * f0.y;
                    accf[m*8+2] = ep1 * f1.x; accf[m*8+3] = ep1 * f1.y;
                    accf[m*8+4] = ep1 * f2.x; accf[m*8+5] = ep1 * f2.y;
                    accf[m*8+6] = ep1 * f3.x; accf[m*8+7] = ep1 * f3.y;
                }
            }
            for (int base = e0; base < e1; base += 32) {
                int cnt = min(32, e1 - base);
                int id = (lane < cnt) ? g_esrc[base + lane] : 0;
                int sa0 = __shfl_sync(0xffffffffu, id, 0);
                const uint4* pa = hb + (size_t)sa0 * 256 + lane;
                for (int e = 0; e < cnt; e++) {
                    int en = (e + 1 < cnt) ? e + 1 : e;
                    int sn = __shfl_sync(0xffffffffu, id, en);
                    const uint4* pn = hb + (size_t)sn * 256 + lane;
                    #pragma unroll
                    for (int m = 0; m < 8; m++) {
                        uint4 t = pa[m * 32];
                        float2 f0 = h2f(t.x), f1 = h2f(t.y);
                        float2 f2 = h2f(t.z), f3 = h2f(t.w);
                        accf[m*8+0] += f0.x; accf[m*8+1] += f0.y;
                        accf[m*8+2] += f1.x; accf[m*8+3] += f1.y;
                        accf[m*8+4] += f2.x; accf[m*8+5] += f2.y;
                        accf[m*8+6] += f3.x; accf[m*8+7] += f3.y;
                    }
                    pa = pn;
                }
            }
            // stage: row = m*8 + (lane>>2), col floats = (lane&3)*8
            #pragma unroll
            for (int m = 0; m < 8; m++) {
                float* p = &sxw[(m * 8 + lr) * PAD + q * 8];
                ((float4*)p)[0] = make_float4(accf[m*8+0], accf[m*8+1],
                                              accf[m*8+2], accf[m*8+3]);
                ((float4*)p)[1] = make_float4(accf[m*8+4], accf[m*8+5],
                                              accf[m*8+6], accf[m*8+7]);
            }
        }
        __syncwarp();

        // ---- hidden: hid = relu(x @ W1 + b1); lane: 8 rows x 4 col-pairs ----
        unsigned long long h2v[32];
        {
            float4 bb0 = *(const float4*)&sb1[q * 8];
            float4 bb1 = *(const float4*)&sb1[q * 8 + 4];
            unsigned long long bp[4] = {pack2(bb0.x, bb0.y), pack2(bb0.z, bb0.w),
                                        pack2(bb1.x, bb1.y), pack2(bb1.z, bb1.w)};
            #pragma unroll
            for (int m = 0; m < 8; m++)
                #pragma unroll
                for (int p = 0; p < 4; p++) h2v[m * 4 + p] = bp[p];
        }
        #pragma unroll
        for (int kb = 0; kb < DIN / 4; kb++) {
            float4 xq[8];
            #pragma unroll
            for (int m = 0; m < 8; m++)
                xq[m] = *(const float4*)&sxw[(lr + 8 * m) * PAD + kb * 4];
            #pragma unroll
            for (int kk = 0; kk < 4; kk++) {
                int k = kb * 4 + kk;
                float4 w0 = *(const float4*)&sW1[k * 32 + q * 8];
                float4 w1 = *(const float4*)&sW1[k * 32 + q * 8 + 4];
                unsigned long long wp[4] = {pack2(w0.x, w0.y), pack2(w0.z, w0.w),
                                            pack2(w1.x, w1.y), pack2(w1.z, w1.w)};
                #pragma unroll
                for (int m = 0; m < 8; m++) {
                    float xv = (kk == 0) ? xq[m].x : (kk == 1) ? xq[m].y
                             : (kk == 2) ? xq[m].z : xq[m].w;
                    unsigned long long xa = pack2dup(xv);
                    #pragma unroll
                    for (int p = 0; p < 4; p++)
                        fma2(h2v[m * 4 + p], xa, wp[p]);
                }
            }
        }
        __syncwarp();   // all x reads done before hid overwrites the buffer
        #pragma unroll
        for (int m = 0; m < 8; m++) {
            float2 p0 = unpack2(h2v[m * 4 + 0]);
            float2 p1 = unpack2(h2v[m * 4 + 1]);
            float2 p2 = unpack2(h2v[m * 4 + 2]);
            float2 p3 = unpack2(h2v[m * 4 + 3]);
            float* p = &sxw[(lr + 8 * m) * PAD + q * 8];
            ((float4*)p)[0] = make_float4(fmaxf(p0.x, 0.f), fmaxf(p0.y, 0.f),
                                          fmaxf(p1.x, 0.f), fmaxf(p1.y, 0.f));
            ((float4*)p)[1] = make_float4(fmaxf(p2.x, 0.f), fmaxf(p2.y, 0.f),
                                          fmaxf(p3.x, 0.f), fmaxf(p3.y, 0.f));
        }
        __syncwarp();

        // ---- output: out = hid @ W2 + b2 ----
        unsigned long long o2[32];
        {
            float4 bb0 = *(const float4*)&sb2[q * 8];
            float4 bb1 = *(const float4*)&sb2[q * 8 + 4];
            unsigned long long bp[4] = {pack2(bb0.x, bb0.y), pack2(bb0.z, bb0.w),
                                        pack2(bb1.x, bb1.y), pack2(bb1.z, bb1.w)};
            #pragma unroll
            for (int m = 0; m < 8; m++)
                #pragma unroll
                for (int p = 0; p < 4; p++) o2[m * 4 + p] = bp[p];
        }
        #pragma unroll
        for (int jb = 0; jb < 8; jb++) {
            float4 hq[8];
            #pragma unroll
            for (int m = 0; m < 8; m++)
                hq[m] = *(const float4*)&sxw[(lr + 8 * m) * PAD + jb * 4];
            #pragma unroll
            for (int jj = 0; jj < 4; jj++) {
                int j = jb * 4 + jj;
                float4 w0 = *(const float4*)&sW2[j * 32 + q * 8];
                float4 w1 = *(const float4*)&sW2[j * 32 + q * 8 + 4];
                unsigned long long wp[4] = {pack2(w0.x, w0.y), pack2(w0.z, w0.w),
                                            pack2(w1.x, w1.y), pack2(w1.z, w1.w)};
                #pragma unroll
                for (int m = 0; m < 8; m++) {
                    float hv = (jj == 0) ? hq[m].x : (jj == 1) ? hq[m].y
                             : (jj == 2) ? hq[m].z : hq[m].w;
                    unsigned long long ha = pack2dup(hv);
                    #pragma unroll
                    for (int p = 0; p < 4; p++)
                        fma2(o2[m * 4 + p], ha, wp[p]);
                }
            }
        }
        __syncwarp();   // hid reads done before next iteration stages x

        if (!POOL) {
            // store fp16: row = lr+8m, 8 half cols at q*8 -> one uint4
            uint4* ob = g_hh[out_buf] + (size_t)n * 256;
            #pragma unroll
            for (int m = 0; m < 8; m++) {
                float2 p0 = unpack2(o2[m * 4 + 0]);
                float2 p1 = unpack2(o2[m * 4 + 1]);
                float2 p2 = unpack2(o2[m * 4 + 2]);
                float2 p3 = unpack2(o2[m * 4 + 3]);
                float v[8] = {p0.x, p0.y, p1.x, p1.y, p2.x, p2.y, p3.x, p3.y};
                if (RELU_OUT) {
                    #pragma unroll
                    for (int i = 0; i < 8; i++) v[i] = fmaxf(v[i], 0.0f);
                }
                uint4 o;
                o.x = f2h(v[0], v[1]); o.y = f2h(v[2], v[3]);
                o.z = f2h(v[4], v[5]); o.w = f2h(v[6], v[7]);
                int grow = lr + 8 * m;
                ob[grow * 4 + q] = o;
            }
        } else {
            // sum over lane's 8 rows, then over lr (lane bits 2..4) -> all 64
            float o[8];
            #pragma unroll
            for (int i = 0; i < 8; i++) o[i] = 0.0f;
            #pragma unroll
            for (int m = 0; m < 8; m++) {
                float2 p0 = unpack2(o2[m * 4 + 0]);
                float2 p1 = unpack2(o2[m * 4 + 1]);
                float2 p2 = unpack2(o2[m * 4 + 2]);
                float2 p3 = unpack2(o2[m * 4 + 3]);
                o[0] += p0.x; o[1] += p0.y; o[2] += p1.x; o[3] += p1.y;
                o[4] += p2.x; o[5] += p2.y; o[6] += p3.x; o[7] += p3.y;
            }
            #pragma unroll
            for (int s = 4; s <= 16; s <<= 1) {
                #pragma unroll
                for (int i = 0; i < 8; i++)
                    o[i] += __shfl_xor_sync(0xffffffffu, o[i], s);
            }
            if (lane < 4) {
                float* p = &dout[n * 32 + q * 8];
                ((float4*)p)[0] = make_float4(o[0], o[1], o[2], o[3]);
                ((float4*)p)[1] = make_float4(o[4], o[5], o[6], o[7]);
            }
        }
    }
}

// ---------------------------------------------------------------------------
extern "C" void kernel_launch(void* const* d_in, const int* in_sizes, int n_in,
                              void* d_out, int out_size)
{
    const float* W    = (const float*)d_in[0];   // [6400, 64, 16]
    const int*   ei   = (const int*)d_in[1];     // [2, E] row-major
    const float* eps  = (const float*)d_in[2];   // [3]
    const float* W1_0 = (const float*)d_in[3];
    const float* b1_0 = (const float*)d_in[4];
    const float* W2_0 = (const float*)d_in[5];
    const float* b2_0 = (const float*)d_in[6];
    const float* W1_1 = (const float*)d_in[7];
    const float* b1_1 = (const float*)d_in[8];
    const float* W2_1 = (const float*)d_in[9];
    const float* b2_1 = (const float*)d_in[10];
    const float* W1_2 = (const float*)d_in[11];
    const float* b1_2 = (const float*)d_in[12];
    const float* W2_2 = (const float*)d_in[13];
    const float* b2_2 = (const float*)d_in[14];
    float* out = (float*)d_out;

    const int* src = ei;
    const int* dst = ei + EDGES;

    const int DYN = 8 * 64 * 36 * (int)sizeof(float);   // 73728 B
    cudaFuncSetAttribute(k_layer<16, false, true, false>,
                         cudaFuncAttributeMaxDynamicSharedMemorySize, DYN);
    cudaFuncSetAttribute(k_layer<32, true, true, false>,
                         cudaFuncAttributeMaxDynamicSharedMemorySize, DYN);
    cudaFuncSetAttribute(k_layer<32, true, false, true>,
                         cudaFuncAttributeMaxDynamicSharedMemorySize, DYN);

    // CSR build (g_cnt / g_work are zero at load; k_scan re-zeroes each call)
    k_count<<<(EDGES + 255) / 256, 256>>>(dst);          // launch 0
    k_scan<<<1, 1024>>>();                                // launch 1
    k_scatter<<<(EDGES + 255) / 256, 256>>>(src, dst);   // launch 2

    const int GRID = 296;   // one persistent wave: 2 blocks x 148 SMs

    // Layer 0: input W fp32 (D=16) -> g_hh[0] fp16 (relu)   -- launch 3
    k_layer<16, false, true, false><<<GRID, 256, DYN>>>(W, 0, 0, eps, 0,
                                                        W1_0, b1_0, W2_0, b2_0, nullptr);
    // Layer 1: g_hh[0] -> g_hh[1] fp16 (relu)               -- launch 4
    k_layer<32, true, true, false><<<GRID, 256, DYN>>>(nullptr, 0, 1, eps, 1,
                                                       W1_1, b1_1, W2_1, b2_1, nullptr);
    // Layer 2: g_hh[1] -> pooled fp32 d_out (no relu)       -- launch 5
    k_layer<32, true, false, true><<<GRID, 256, DYN>>>(nullptr, 1, 0, eps, 2,
                                                       W1_2, b1_2, W2_2, b2_2, out);
}